// round 1
// baseline (speedup 1.0000x reference)
#include <cuda_runtime.h>

#define NROWS 8192
#define NCOLS 2048
#define ORDER 8
#define GRID_MAIN 296
#define TPB 512

// T' = diag(rn) * T * diag(rn), 8x8, produced by setup kernel.
__device__ float g_Tp[ORDER * ORDER];

// ---------------------------------------------------------------------------
// Setup: Gram matrix of raw v rows -> row norms -> WY "T" factor -> T'.
// One block, 256 threads; each thread owns 8 consecutive columns.
// ---------------------------------------------------------------------------
__global__ void setup_Tp(const float* __restrict__ v) {
    __shared__ float gpart[8][36];
    const int t = threadIdx.x;
    const int lane = t & 31, w = t >> 5;
    const int c0 = t * 8;

    float vr[ORDER][8];
#pragma unroll
    for (int k = 0; k < ORDER; ++k) {
        float4 a = *reinterpret_cast<const float4*>(v + k * NCOLS + c0);
        float4 b = *reinterpret_cast<const float4*>(v + k * NCOLS + c0 + 4);
        vr[k][0] = a.x; vr[k][1] = a.y; vr[k][2] = a.z; vr[k][3] = a.w;
        vr[k][4] = b.x; vr[k][5] = b.y; vr[k][6] = b.z; vr[k][7] = b.w;
    }

    float G[36];
    {
        int idx = 0;
#pragma unroll
        for (int i = 0; i < ORDER; ++i)
#pragma unroll
            for (int k = i; k < ORDER; ++k) {
                float s = 0.f;
#pragma unroll
                for (int j = 0; j < 8; ++j) s = fmaf(vr[i][j], vr[k][j], s);
                G[idx++] = s;
            }
    }
#pragma unroll
    for (int e = 0; e < 36; ++e) {
#pragma unroll
        for (int m = 16; m >= 1; m >>= 1)
            G[e] += __shfl_xor_sync(0xffffffffu, G[e], m);
    }
    if (lane == 0) {
#pragma unroll
        for (int e = 0; e < 36; ++e) gpart[w][e] = G[e];
    }
    __syncthreads();

    if (t == 0) {
        float acc[36];
        for (int e = 0; e < 36; ++e) {
            float s = 0.f;
            for (int ww = 0; ww < 8; ++ww) s += gpart[ww][e];
            acc[e] = s;
        }
        float Gs[ORDER][ORDER];
        int id2 = 0;
        for (int i = 0; i < ORDER; ++i)
            for (int k = i; k < ORDER; ++k) {
                Gs[i][k] = acc[id2];
                Gs[k][i] = acc[id2];
                ++id2;
            }
        float rn[ORDER];
        for (int i = 0; i < ORDER; ++i) rn[i] = 1.0f / sqrtf(Gs[i][i]);
        float Gh[ORDER][ORDER];
        for (int i = 0; i < ORDER; ++i)
            for (int k = 0; k < ORDER; ++k) Gh[i][k] = Gs[i][k] * rn[i] * rn[k];
        // Compact-WY: Q = H0 H1 ... H7 = I - V T V^T (V columns = normalized v rows)
        float T[ORDER][ORDER];
        for (int i = 0; i < ORDER; ++i)
            for (int k = 0; k < ORDER; ++k) T[i][k] = 0.f;
        for (int i = 0; i < ORDER; ++i) T[i][i] = 2.f;
        for (int c = 1; c < ORDER; ++c)
            for (int r = 0; r < c; ++r) {
                float s = 0.f;
                for (int m = r; m < c; ++m) s += T[r][m] * Gh[m][c];
                T[r][c] = -2.f * s;
            }
        // Fold normalization into T so main kernel uses raw v directly.
        for (int i = 0; i < ORDER; ++i)
            for (int k = 0; k < ORDER; ++k)
                g_Tp[i * ORDER + k] = rn[i] * T[i][k] * rn[k];
    }
}

// ---------------------------------------------------------------------------
// Main fused kernel: y = (x - (x v^T) T' v) * d + bias
// 512 threads/block; thread owns 4 consecutive columns (float4).
// Grid-stride over rows with a 2-deep load pipeline.
// ---------------------------------------------------------------------------
__global__ void __launch_bounds__(TPB) orth_dense_kernel(
    const float* __restrict__ x, const float* __restrict__ v,
    const float* __restrict__ d, const float* __restrict__ bias,
    float* __restrict__ y)
{
    __shared__ float wsum[16 * 10];  // 16 warps x 8 partials (stride 10: bank-safe)
    __shared__ float bfin[8];
    __shared__ float Ts[64];

    const int t = threadIdx.x, lane = t & 31, w = t >> 5;
    const int c0 = t * 4;

    if (t < 64) Ts[t] = g_Tp[t];

    float4 V4[ORDER];
#pragma unroll
    for (int k = 0; k < ORDER; ++k)
        V4[k] = *reinterpret_cast<const float4*>(v + k * NCOLS + c0);
    const float4 d4  = *reinterpret_cast<const float4*>(d + c0);
    const float4 bs4 = *reinterpret_cast<const float4*>(bias + c0);
    __syncthreads();

    const int r0 = blockIdx.x;
    const int nr = (NROWS - r0 + GRID_MAIN - 1) / GRID_MAIN;

    const float* xp = x + c0;
    float*       yp = y + c0;

    float4 xa, xb;
    xa = *reinterpret_cast<const float4*>(xp + (size_t)r0 * NCOLS);
    xb = (nr > 1) ? *reinterpret_cast<const float4*>(xp + (size_t)(r0 + GRID_MAIN) * NCOLS)
                  : make_float4(0.f, 0.f, 0.f, 0.f);

    for (int i = 0; i < nr; ++i) {
        const float4 cur = xa;
        xa = xb;
        xb = (i + 2 < nr)
               ? *reinterpret_cast<const float4*>(xp + (size_t)(r0 + (i + 2) * GRID_MAIN) * NCOLS)
               : make_float4(0.f, 0.f, 0.f, 0.f);

        // per-thread partial dots against the 8 reflection vectors
        float p[8];
#pragma unroll
        for (int k = 0; k < 8; ++k) {
            float s = cur.x * V4[k].x;
            s = fmaf(cur.y, V4[k].y, s);
            s = fmaf(cur.z, V4[k].z, s);
            s = fmaf(cur.w, V4[k].w, s);
            p[k] = s;
        }
        // warp reduce 8 values with folding: 23 shfl total; lane L ends with k = L&7
#pragma unroll
        for (int k = 0; k < 8; ++k) {
            p[k] += __shfl_xor_sync(0xffffffffu, p[k], 16);
            p[k] += __shfl_xor_sync(0xffffffffu, p[k], 8);
        }
        {
            const bool h4 = (lane & 4) != 0;
            float q[4];
#pragma unroll
            for (int j = 0; j < 4; ++j) {
                float keep = h4 ? p[j + 4] : p[j];
                float send = h4 ? p[j] : p[j + 4];
                q[j] = keep + __shfl_xor_sync(0xffffffffu, send, 4);
            }
            const bool h2 = (lane & 2) != 0;
            float r2[2];
#pragma unroll
            for (int j = 0; j < 2; ++j) {
                float keep = h2 ? q[j + 2] : q[j];
                float send = h2 ? q[j] : q[j + 2];
                r2[j] = keep + __shfl_xor_sync(0xffffffffu, send, 2);
            }
            const bool h1 = (lane & 1) != 0;
            float keep = h1 ? r2[1] : r2[0];
            float send = h1 ? r2[0] : r2[1];
            float s = keep + __shfl_xor_sync(0xffffffffu, send, 1);
            if (lane < 8) wsum[w * 10 + lane] = s;
        }
        __syncthreads();

        if (w == 0) {
            const int k = lane & 7, g = lane >> 3;  // 4 groups of 4 warps
            float a = wsum[(g * 4 + 0) * 10 + k] + wsum[(g * 4 + 1) * 10 + k]
                    + wsum[(g * 4 + 2) * 10 + k] + wsum[(g * 4 + 3) * 10 + k];
            a += __shfl_xor_sync(0xffffffffu, a, 8);
            a += __shfl_xor_sync(0xffffffffu, a, 16);
            // b[k] = sum_i a[i] * T'[i][k]
            float bk = 0.f;
#pragma unroll
            for (int ii = 0; ii < 8; ++ii) {
                float ai = __shfl_sync(0xffffffffu, a, ii);
                bk = fmaf(ai, Ts[ii * 8 + k], bk);
            }
            if (lane < 8) bfin[lane] = bk;
        }
        __syncthreads();

        float bb[8];
#pragma unroll
        for (int k = 0; k < 8; ++k) bb[k] = bfin[k];

        float4 accv = cur;
#pragma unroll
        for (int k = 0; k < 8; ++k) {
            const float nb = -bb[k];
            accv.x = fmaf(nb, V4[k].x, accv.x);
            accv.y = fmaf(nb, V4[k].y, accv.y);
            accv.z = fmaf(nb, V4[k].z, accv.z);
            accv.w = fmaf(nb, V4[k].w, accv.w);
        }
        float4 out;
        out.x = fmaf(accv.x, d4.x, bs4.x);
        out.y = fmaf(accv.y, d4.y, bs4.y);
        out.z = fmaf(accv.z, d4.z, bs4.z);
        out.w = fmaf(accv.w, d4.w, bs4.w);
        *reinterpret_cast<float4*>(yp + (size_t)(r0 + i * GRID_MAIN) * NCOLS) = out;
    }
}

extern "C" void kernel_launch(void* const* d_in, const int* in_sizes, int n_in,
                              void* d_out, int out_size) {
    const float* x    = (const float*)d_in[0];
    const float* v    = (const float*)d_in[1];
    const float* dvec = (const float*)d_in[2];
    const float* bias = (const float*)d_in[3];
    float* y = (float*)d_out;
    (void)in_sizes; (void)n_in; (void)out_size;

    setup_Tp<<<1, 256>>>(v);
    orth_dense_kernel<<<GRID_MAIN, TPB>>>(x, v, dvec, bias, y);
}

// round 2
// speedup vs baseline: 1.3341x; 1.3341x over previous
#include <cuda_runtime.h>

#define NROWS 8192
#define NCOLS 2048
#define ORDER 8
#define NB    148
#define TPB   512
#define TILE  8
#define NTILES 7   // every block has 55 or 56 rows -> always 7 tiles

__device__ __forceinline__ float4 ldg4_cs(const float* p) {
    return __ldcs(reinterpret_cast<const float4*>(p));
}

__global__ void __launch_bounds__(TPB, 1) orth_fused(
    const float* __restrict__ x, const float* __restrict__ v,
    const float* __restrict__ d, const float* __restrict__ bias,
    float* __restrict__ y)
{
    __shared__ float gpart[16 * 40];    // per-warp Gram partials (36 used)
    __shared__ float sG[64];            // full Gram 8x8
    __shared__ float Ts[64];            // T' = rn * T * rn
    __shared__ float wsum[TILE * 132];  // per-row, per-warp dot partials
    __shared__ float bsh[TILE * 8];     // b = a T' per tile row

    const int t = threadIdx.x, lane = t & 31, w = t >> 5;
    const int c0 = t * 4;

    // ---- per-thread V slice (lives in registers for the whole kernel) ----
    float4 V4[ORDER];
#pragma unroll
    for (int k = 0; k < ORDER; ++k)
        V4[k] = *reinterpret_cast<const float4*>(v + k * NCOLS + c0);
    const float4 d4  = *reinterpret_cast<const float4*>(d + c0);
    const float4 bs4 = *reinterpret_cast<const float4*>(bias + c0);

    // ================= Prologue: Gram -> T' (per block, no 2nd launch) ====
    {
        float G[36];
        int idx = 0;
#pragma unroll
        for (int i = 0; i < ORDER; ++i)
#pragma unroll
            for (int k = i; k < ORDER; ++k) {
                float s = V4[i].x * V4[k].x;
                s = fmaf(V4[i].y, V4[k].y, s);
                s = fmaf(V4[i].z, V4[k].z, s);
                s = fmaf(V4[i].w, V4[k].w, s);
                G[idx++] = s;
            }
#pragma unroll
        for (int e = 0; e < 36; ++e) {
#pragma unroll
            for (int m = 16; m >= 1; m >>= 1)
                G[e] += __shfl_xor_sync(0xffffffffu, G[e], m);
        }
        if (lane == 0) {
#pragma unroll
            for (int e = 0; e < 36; ++e) gpart[w * 40 + e] = G[e];
        }
    }
    __syncthreads();
    if (t < 36) {
        float s = 0.f;
#pragma unroll
        for (int ww = 0; ww < 16; ++ww) s += gpart[ww * 40 + t];
        gpart[t] = s;
    }
    __syncthreads();
    if (t == 0) {
        int idx = 0;
        for (int i = 0; i < ORDER; ++i)
            for (int k = i; k < ORDER; ++k) {
                sG[i * 8 + k] = gpart[idx];
                sG[k * 8 + i] = gpart[idx];
                ++idx;
            }
        float rn[ORDER];
        for (int i = 0; i < ORDER; ++i) rn[i] = 1.0f / sqrtf(sG[i * 8 + i]);
        // compact-WY T recursion on the normalized Gram
        for (int i = 0; i < ORDER; ++i)
            for (int k = 0; k < ORDER; ++k) Ts[i * 8 + k] = 0.f;
        for (int i = 0; i < ORDER; ++i) Ts[i * 8 + i] = 2.f;
        for (int c = 1; c < ORDER; ++c)
            for (int r = 0; r < c; ++r) {
                float s = 0.f;
                for (int m = r; m < c; ++m)
                    s += Ts[r * 8 + m] * (sG[m * 8 + c] * rn[m] * rn[c]);
                Ts[r * 8 + c] = -2.f * s;
            }
        // fold normalization so raw v works directly
        for (int i = 0; i < ORDER; ++i)
            for (int k = 0; k < ORDER; ++k)
                Ts[i * 8 + k] *= rn[i] * rn[k];
    }
    __syncthreads();

    // ================= Main loop: 8-row tiles, 2 barriers per tile ========
    const int bid = blockIdx.x;
    const int r0 = bid * 55 + min(bid, 52);          // 52 blocks get 56 rows
    const int nr = 55 + (bid < 52 ? 1 : 0);

    const float* xp = x + c0;
    float*       yp = y + c0;

    float4 cur[TILE];

#pragma unroll 1
    for (int tt = 0; tt < NTILES; ++tt) {
        const int rbase = tt * TILE;

        // load this tile (8 independent LDG.128 in flight per warp)
#pragma unroll
        for (int j = 0; j < TILE; ++j) {
            const int jr = rbase + j;
            cur[j] = (jr < nr) ? ldg4_cs(xp + (size_t)(r0 + jr) * NCOLS)
                               : make_float4(0.f, 0.f, 0.f, 0.f);
        }

        // L2 prefetch of next tile (no register cost), 4 lines/warp/row
        if (tt + 1 < NTILES && (lane & 7) == 0) {
#pragma unroll
            for (int j = 0; j < TILE; ++j) {
                const int jr = rbase + TILE + j;
                if (jr < nr) {
                    const float* pf = xp + (size_t)(r0 + jr) * NCOLS;
                    asm volatile("prefetch.global.L2 [%0];" :: "l"(pf));
                }
            }
        }

        // -------- phase 1: per-row dot partials + warp reduce ------------
#pragma unroll
        for (int j = 0; j < TILE; ++j) {
            const float4 cu = cur[j];
            float p[8];
#pragma unroll
            for (int k = 0; k < 8; ++k) {
                float s = cu.x * V4[k].x;
                s = fmaf(cu.y, V4[k].y, s);
                s = fmaf(cu.z, V4[k].z, s);
                s = fmaf(cu.w, V4[k].w, s);
                p[k] = s;
            }
#pragma unroll
            for (int k = 0; k < 8; ++k) {
                p[k] += __shfl_xor_sync(0xffffffffu, p[k], 16);
                p[k] += __shfl_xor_sync(0xffffffffu, p[k], 8);
            }
            {
                const bool h4 = (lane & 4) != 0;
                float q[4];
#pragma unroll
                for (int jj = 0; jj < 4; ++jj) {
                    float keep = h4 ? p[jj + 4] : p[jj];
                    float send = h4 ? p[jj] : p[jj + 4];
                    q[jj] = keep + __shfl_xor_sync(0xffffffffu, send, 4);
                }
                const bool h2 = (lane & 2) != 0;
                float r2[2];
#pragma unroll
                for (int jj = 0; jj < 2; ++jj) {
                    float keep = h2 ? q[jj + 2] : q[jj];
                    float send = h2 ? q[jj] : q[jj + 2];
                    r2[jj] = keep + __shfl_xor_sync(0xffffffffu, send, 2);
                }
                const bool h1 = (lane & 1) != 0;
                float keep = h1 ? r2[1] : r2[0];
                float send = h1 ? r2[0] : r2[1];
                float s = keep + __shfl_xor_sync(0xffffffffu, send, 1);
                if (lane < 8) wsum[j * 132 + w * 8 + lane] = s;
            }
        }
        __syncthreads();

        // -------- phase 2: cross-warp reduce + T' (64 threads) -----------
        if (t < 64) {
            const int row = t >> 3, k = t & 7;
            float a = 0.f;
#pragma unroll
            for (int ww = 0; ww < 16; ++ww) a += wsum[row * 132 + ww * 8 + k];
            float bk = 0.f;
#pragma unroll
            for (int i = 0; i < 8; ++i) {
                float ai = __shfl_sync(0xffffffffu, a, (lane & 24) | i);
                bk = fmaf(ai, Ts[i * 8 + k], bk);
            }
            bsh[row * 8 + k] = bk;
        }
        __syncthreads();

        // -------- phase 3: correction + scale + store (x still in regs) --
#pragma unroll
        for (int j = 0; j < TILE; ++j) {
            const int jr = rbase + j;
            if (jr < nr) {
                const float4 b0 = *reinterpret_cast<const float4*>(&bsh[j * 8]);
                const float4 b1 = *reinterpret_cast<const float4*>(&bsh[j * 8 + 4]);
                const float bb[8] = {b0.x, b0.y, b0.z, b0.w, b1.x, b1.y, b1.z, b1.w};
                float4 acc = cur[j];
#pragma unroll
                for (int k = 0; k < 8; ++k) {
                    const float nb = -bb[k];
                    acc.x = fmaf(nb, V4[k].x, acc.x);
                    acc.y = fmaf(nb, V4[k].y, acc.y);
                    acc.z = fmaf(nb, V4[k].z, acc.z);
                    acc.w = fmaf(nb, V4[k].w, acc.w);
                }
                float4 out;
                out.x = fmaf(acc.x, d4.x, bs4.x);
                out.y = fmaf(acc.y, d4.y, bs4.y);
                out.z = fmaf(acc.z, d4.z, bs4.z);
                out.w = fmaf(acc.w, d4.w, bs4.w);
                __stcs(reinterpret_cast<float4*>(yp + (size_t)(r0 + jr) * NCOLS), out);
            }
        }
    }
}

extern "C" void kernel_launch(void* const* d_in, const int* in_sizes, int n_in,
                              void* d_out, int out_size) {
    const float* x    = (const float*)d_in[0];
    const float* v    = (const float*)d_in[1];
    const float* dvec = (const float*)d_in[2];
    const float* bias = (const float*)d_in[3];
    float* y = (float*)d_out;
    (void)in_sizes; (void)n_in; (void)out_size;

    orth_fused<<<NB, TPB>>>(x, v, dvec, bias, y);
}